// round 5
// baseline (speedup 1.0000x reference)
#include <cuda_runtime.h>
#include <math.h>
#include <stdint.h>

#define Bsz   4
#define Nseq  2048
#define Emb   512
#define Hn    8
#define HDm   64
#define HID   1536
#define ROWS  (Bsz * Nseq)   // 8192

// ---------------- scratch (device globals; no allocation allowed) ----------
__device__ float g_xn [ROWS * Emb];
__device__ float g_qkv[ROWS * 3 * Emb];
__device__ float g_x1 [ROWS * Emb];
__device__ float g_xn2[ROWS * Emb];
__device__ float g_hid[ROWS * HID];

// ---------------- small helpers ----------------------------------------------
__device__ __forceinline__ uint32_t smem_u32(const void* p) {
    uint32_t a;
    asm("{ .reg .u64 t; cvta.to.shared.u64 t, %1; cvt.u32.u64 %0, t; }"
        : "=r"(a) : "l"(p));
    return a;
}
__device__ __forceinline__ void cp_async16(uint32_t saddr, const void* gptr) {
    asm volatile("cp.async.cg.shared.global [%0], [%1], 16;"
                 :: "r"(saddr), "l"(gptr) : "memory");
}
#define CP_COMMIT() asm volatile("cp.async.commit_group;" ::: "memory")
#define CP_WAIT1()  asm volatile("cp.async.wait_group 1;" ::: "memory")
#define CP_WAIT0()  asm volatile("cp.async.wait_group 0;" ::: "memory")

__device__ __forceinline__ float gelu_exact(float x) {
    return 0.5f * x * (1.0f + erff(x * 0.70710678118654752f));
}
__device__ __forceinline__ float tf32r(float x) {
    unsigned u;
    asm("cvt.rna.tf32.f32 %0, %1;" : "=r"(u) : "f"(x));
    return __uint_as_float(u);
}
__device__ __forceinline__ float4 tf32r4(float4 v) {
    float4 r;
    r.x = tf32r(v.x); r.y = tf32r(v.y); r.z = tf32r(v.z); r.w = tf32r(v.w);
    return r;
}
__device__ __forceinline__ void mma_tf32(
    float* d, const unsigned* a, const unsigned* b)
{
    asm volatile(
        "mma.sync.aligned.m16n8k8.row.col.f32.tf32.tf32.f32 "
        "{%0,%1,%2,%3}, {%4,%5,%6,%7}, {%8,%9}, {%0,%1,%2,%3};"
        : "+f"(d[0]), "+f"(d[1]), "+f"(d[2]), "+f"(d[3])
        : "r"(a[0]), "r"(a[1]), "r"(a[2]), "r"(a[3]),
          "r"(b[0]), "r"(b[1]));
}

// ---------------- LayerNorm (optionally fused residual add) ----------------
__global__ void __launch_bounds__(256) ln_kernel(
    const float* __restrict__ x, const float* __restrict__ resid,
    const float* __restrict__ g, const float* __restrict__ bb,
    float* __restrict__ out, float* __restrict__ xsum)
{
    int row = blockIdx.x;
    int tid = threadIdx.x;
    const float2* xr = (const float2*)(x + (size_t)row * Emb);
    float2 v = xr[tid];
    if (resid) {
        const float2* rr = (const float2*)(resid + (size_t)row * Emb);
        float2 r = rr[tid];
        v.x += r.x; v.y += r.y;
        ((float2*)(xsum + (size_t)row * Emb))[tid] = v;
    }
    float s  = v.x + v.y;
    float sq = v.x * v.x + v.y * v.y;
    #pragma unroll
    for (int o = 16; o > 0; o >>= 1) {
        s  += __shfl_xor_sync(0xffffffffu, s,  o);
        sq += __shfl_xor_sync(0xffffffffu, sq, o);
    }
    __shared__ float ss[8], sqs[8];
    int w = tid >> 5, lane = tid & 31;
    if (lane == 0) { ss[w] = s; sqs[w] = sq; }
    __syncthreads();
    float st = 0.f, sqt = 0.f;
    #pragma unroll
    for (int i = 0; i < 8; i++) { st += ss[i]; sqt += sqs[i]; }
    float mu   = st * (1.0f / Emb);
    float var  = sqt * (1.0f / Emb) - mu * mu;
    float rstd = rsqrtf(var + 1e-5f);
    float2 gg  = ((const float2*)g)[tid];
    float2 bv  = ((const float2*)bb)[tid];
    float2 o;
    o.x = (v.x - mu) * rstd * gg.x + bv.x;
    o.y = (v.y - mu) * rstd * gg.y + bv.y;
    ((float2*)(out + (size_t)row * Emb))[tid] = o;
}

// ---------------- TF32 mma.sync GEMM, cp.async 3-stage pipeline --------------
// C[M,N] = A[M,K] @ W[K,N] + bias (+gelu)(+resid)
// CTA 128x128, BK=32, 256 thr = 8 warps, warp tile 32x64 (layouts verified R2).
// As: [m][k] stride 36 (rows 144B, 16B-aligned); Bs: [k][n] stride 136 (544B).
#define AST 36
#define BST 136
#define STGF (128 * AST + 32 * BST)              // floats per stage = 8960
#define GEMM_SMEM (3 * STGF * 4)                 // 107520 B

template<int ACT, bool RES>
__global__ void __launch_bounds__(256, 2) tf32_gemm_kernel(
    const float* __restrict__ A, const float* __restrict__ W,
    const float* __restrict__ bias, const float* __restrict__ R,
    float* __restrict__ C, int K, int N)
{
    extern __shared__ float sm[];
    int tid  = threadIdx.x;
    int lane = tid & 31;
    int wid  = tid >> 5;
    int wm   = wid & 3;
    int wn   = wid >> 2;
    int bm   = blockIdx.y, bn = blockIdx.x;
    int g    = lane >> 2, q = lane & 3;

    // cp.async mapping: A row am (0..127), 16-float half ah; B row bk (0..31), 16-float slice
    int am = tid >> 1;
    int ah = (tid & 1) * 16;
    int bk = tid >> 3;
    int bh = (tid & 7) * 16;
    const float* Ag = A + (size_t)(bm * 128 + am) * K + ah;
    const float* Wg = W + (size_t)bk * N + bn * 128 + bh;
    uint32_t sbase = smem_u32(sm);
    uint32_t sA = sbase + (uint32_t)(am * AST + ah) * 4;
    uint32_t sB = sbase + (uint32_t)(128 * AST + bk * BST + bh) * 4;

    int NT = K / 32;
    #define ISSUE(t)                                                          \
        {                                                                     \
            int _s = (t) % 3;                                                 \
            const float* _a = Ag + (t) * 32;                                  \
            const float* _b = Wg + (size_t)((t) * 32) * N;                    \
            uint32_t _sa = sA + _s * (STGF * 4);                              \
            uint32_t _sb = sB + _s * (STGF * 4);                              \
            _Pragma("unroll")                                                 \
            for (int j = 0; j < 4; j++) cp_async16(_sa + j * 16, _a + j * 4); \
            _Pragma("unroll")                                                 \
            for (int j = 0; j < 4; j++) cp_async16(_sb + j * 16, _b + j * 4); \
            CP_COMMIT();                                                      \
        }

    ISSUE(0);
    ISSUE(1);

    float acc[2][8][4] = {};

    for (int t = 0; t < NT; t++) {
        if (t == NT - 1) { CP_WAIT0(); } else { CP_WAIT1(); }
        __syncthreads();
        if (t + 2 < NT) ISSUE(t + 2);

        const unsigned* asu = (const unsigned*)(sm + (t % 3) * STGF)
                              + wm * 32 * AST;
        const unsigned* bsu = (const unsigned*)(sm + (t % 3) * STGF + 128 * AST)
                              + wn * 64;
        #pragma unroll
        for (int k8 = 0; k8 < 4; k8++) {
            int kk = k8 * 8;
            unsigned a[2][4], b[8][2];
            #pragma unroll
            for (int mf = 0; mf < 2; mf++) {
                a[mf][0] = asu[(mf * 16 + g)     * AST + kk + q];
                a[mf][1] = asu[(mf * 16 + g + 8) * AST + kk + q];
                a[mf][2] = asu[(mf * 16 + g)     * AST + kk + q + 4];
                a[mf][3] = asu[(mf * 16 + g + 8) * AST + kk + q + 4];
            }
            #pragma unroll
            for (int nf = 0; nf < 8; nf++) {
                b[nf][0] = bsu[(kk + q)     * BST + nf * 8 + g];
                b[nf][1] = bsu[(kk + q + 4) * BST + nf * 8 + g];
            }
            #pragma unroll
            for (int mf = 0; mf < 2; mf++)
                #pragma unroll
                for (int nf = 0; nf < 8; nf++)
                    mma_tf32(acc[mf][nf], a[mf], b[nf]);
        }
        __syncthreads();
    }

    // epilogue (verified R2)
    int row0 = bm * 128 + wm * 32 + g;
    int col0 = bn * 128 + wn * 64 + 2 * q;
    #pragma unroll
    for (int nf = 0; nf < 8; nf++) {
        int c = col0 + nf * 8;
        float bx = bias[c], by = bias[c + 1];
        #pragma unroll
        for (int mf = 0; mf < 2; mf++) {
            int r0 = row0 + mf * 16;
            float v0x = acc[mf][nf][0] + bx;
            float v0y = acc[mf][nf][1] + by;
            float v1x = acc[mf][nf][2] + bx;
            float v1y = acc[mf][nf][3] + by;
            if (ACT == 1) {
                v0x = gelu_exact(v0x); v0y = gelu_exact(v0y);
                v1x = gelu_exact(v1x); v1y = gelu_exact(v1y);
            }
            if (RES) {
                const float2 r0v = *(const float2*)&R[(size_t)r0 * N + c];
                const float2 r1v = *(const float2*)&R[(size_t)(r0 + 8) * N + c];
                v0x += r0v.x; v0y += r0v.y;
                v1x += r1v.x; v1y += r1v.y;
            }
            float2 o0 = {v0x, v0y}, o1 = {v1x, v1y};
            *(float2*)&C[(size_t)r0 * N + c]       = o0;
            *(float2*)&C[(size_t)(r0 + 8) * N + c] = o1;
        }
    }
    #undef ISSUE
}

// ---------------- flash attention, TF32 mma.sync (verified R3) --------------
#define QST 68
#define KST 68
#define VST 72
#define PST 68
#define ATTN_SMEM ((64 * QST + 64 * KST + 64 * VST + 64 * PST) * 4)

__global__ void __launch_bounds__(128) attn_mma_kernel(
    const float* __restrict__ qkv, float* __restrict__ out)
{
    extern __shared__ float sm[];
    float* Qs = sm;
    float* Ks = Qs + 64 * QST;
    float* Vs = Ks + 64 * KST;
    float* Ps = Vs + 64 * VST;

    int tid  = threadIdx.x;
    int lane = tid & 31;
    int w    = tid >> 5;
    int g    = lane >> 2, q = lane & 3;

    int bh = blockIdx.y;
    int b  = bh >> 3, h = bh & 7;
    int q0 = blockIdx.x * 64;
    const float* base = qkv + (size_t)b * Nseq * (3 * Emb) + h * (3 * HDm);

    #pragma unroll
    for (int i = 0; i < 8; i++) {
        int fi  = tid + i * 128;
        int row = fi >> 4;
        int c4  = (fi & 15) * 4;
        float4 v = *(const float4*)(base + (size_t)(q0 + row) * (3 * Emb) + c4);
        *(float4*)&Qs[row * QST + c4] = tf32r4(v);
    }

    float O[8][4] = {};
    float m0 = -1e30f, m1 = -1e30f, l0 = 0.f, l1 = 0.f;

    for (int kb = 0; kb < Nseq / 64; kb++) {
        __syncthreads();
        #pragma unroll
        for (int i = 0; i < 8; i++) {
            int fi  = tid + i * 128;
            int row = fi >> 4;
            int c4  = (fi & 15) * 4;
            const float* gp = base + (size_t)(kb * 64 + row) * (3 * Emb);
            *(float4*)&Ks[row * KST + c4] = tf32r4(*(const float4*)(gp + HDm + c4));
            *(float4*)&Vs[row * VST + c4] = tf32r4(*(const float4*)(gp + 2 * HDm + c4));
        }
        __syncthreads();

        const unsigned* qsu = (const unsigned*)Qs + (w * 16) * QST;
        unsigned af[8][4];
        #pragma unroll
        for (int k8 = 0; k8 < 8; k8++) {
            int kk = k8 * 8;
            af[k8][0] = qsu[(g)     * QST + kk + q];
            af[k8][1] = qsu[(g + 8) * QST + kk + q];
            af[k8][2] = qsu[(g)     * QST + kk + q + 4];
            af[k8][3] = qsu[(g + 8) * QST + kk + q + 4];
        }
        float sacc[8][4] = {};
        const unsigned* ksu = (const unsigned*)Ks;
        #pragma unroll
        for (int nf = 0; nf < 8; nf++) {
            #pragma unroll
            for (int k8 = 0; k8 < 8; k8++) {
                unsigned bfr[2];
                bfr[0] = ksu[(nf * 8 + g) * KST + k8 * 8 + q];
                bfr[1] = ksu[(nf * 8 + g) * KST + k8 * 8 + q + 4];
                mma_tf32(sacc[nf], af[k8], bfr);
            }
        }

        float mx0 = -1e30f, mx1 = -1e30f;
        #pragma unroll
        for (int nf = 0; nf < 8; nf++) {
            sacc[nf][0] *= 0.125f; sacc[nf][1] *= 0.125f;
            sacc[nf][2] *= 0.125f; sacc[nf][3] *= 0.125f;
            mx0 = fmaxf(mx0, fmaxf(sacc[nf][0], sacc[nf][1]));
            mx1 = fmaxf(mx1, fmaxf(sacc[nf][2], sacc[nf][3]));
        }
        mx0 = fmaxf(mx0, __shfl_xor_sync(0xffffffffu, mx0, 1));
        mx0 = fmaxf(mx0, __shfl_xor_sync(0xffffffffu, mx0, 2));
        mx1 = fmaxf(mx1, __shfl_xor_sync(0xffffffffu, mx1, 1));
        mx1 = fmaxf(mx1, __shfl_xor_sync(0xffffffffu, mx1, 2));

        float mn0 = fmaxf(m0, mx0), mn1 = fmaxf(m1, mx1);
        float al0 = __expf(m0 - mn0), al1 = __expf(m1 - mn1);
        m0 = mn0; m1 = mn1;

        float rs0 = 0.f, rs1 = 0.f;
        float* pw = Ps + (w * 16) * PST;
        #pragma unroll
        for (int nf = 0; nf < 8; nf++) {
            float p0 = __expf(sacc[nf][0] - mn0);
            float p1 = __expf(sacc[nf][1] - mn0);
            float p2 = __expf(sacc[nf][2] - mn1);
            float p3 = __expf(sacc[nf][3] - mn1);
            rs0 += p0 + p1; rs1 += p2 + p3;
            pw[(g)     * PST + nf * 8 + 2 * q]     = tf32r(p0);
            pw[(g)     * PST + nf * 8 + 2 * q + 1] = tf32r(p1);
            pw[(g + 8) * PST + nf * 8 + 2 * q]     = tf32r(p2);
            pw[(g + 8) * PST + nf * 8 + 2 * q + 1] = tf32r(p3);
        }
        rs0 += __shfl_xor_sync(0xffffffffu, rs0, 1);
        rs0 += __shfl_xor_sync(0xffffffffu, rs0, 2);
        rs1 += __shfl_xor_sync(0xffffffffu, rs1, 1);
        rs1 += __shfl_xor_sync(0xffffffffu, rs1, 2);
        l0 = l0 * al0 + rs0;
        l1 = l1 * al1 + rs1;

        #pragma unroll
        for (int df = 0; df < 8; df++) {
            O[df][0] *= al0; O[df][1] *= al0;
            O[df][2] *= al1; O[df][3] *= al1;
        }
        __syncwarp();

        const unsigned* psu = (const unsigned*)Ps + (w * 16) * PST;
        unsigned pf[8][4];
        #pragma unroll
        for (int k8 = 0; k8 < 8; k8++) {
            int kk = k8 * 8;
            pf[k8][0] = psu[(g)     * PST + kk + q];
            pf[k8][1] = psu[(g + 8) * PST + kk + q];
            pf[k8][2] = psu[(g)     * PST + kk + q + 4];
            pf[k8][3] = psu[(g + 8) * PST + kk + q + 4];
        }
        const unsigned* vsu = (const unsigned*)Vs;
        #pragma unroll
        for (int df = 0; df < 8; df++) {
            #pragma unroll
            for (int k8 = 0; k8 < 8; k8++) {
                unsigned bfr[2];
                bfr[0] = vsu[(k8 * 8 + q)     * VST + df * 8 + g];
                bfr[1] = vsu[(k8 * 8 + q + 4) * VST + df * 8 + g];
                mma_tf32(O[df], pf[k8], bfr);
            }
        }
    }

    float inv0 = 1.0f / l0, inv1 = 1.0f / l1;
    int r0 = q0 + w * 16 + g;
    int r1 = r0 + 8;
    #pragma unroll
    for (int df = 0; df < 8; df++) {
        int c = h * HDm + df * 8 + 2 * q;
        float2 o0 = {O[df][0] * inv0, O[df][1] * inv0};
        float2 o1 = {O[df][2] * inv1, O[df][3] * inv1};
        *(float2*)&out[((size_t)b * Nseq + r0) * Emb + c] = o0;
        *(float2*)&out[((size_t)b * Nseq + r1) * Emb + c] = o1;
    }
}

// ---------------- launch ------------------------------------------------------
extern "C" void kernel_launch(void* const* d_in, const int* in_sizes, int n_in,
                              void* d_out, int out_size)
{
    (void)in_sizes; (void)n_in; (void)out_size;
    const float* x        = (const float*)d_in[0];
    const float* qkv_w    = (const float*)d_in[1];
    const float* qkv_b    = (const float*)d_in[2];
    const float* fc1_w    = (const float*)d_in[3];
    const float* fc1_b    = (const float*)d_in[4];
    const float* fc2_w    = (const float*)d_in[5];
    const float* fc2_b    = (const float*)d_in[6];
    const float* ln_att_g = (const float*)d_in[7];
    const float* ln_att_b = (const float*)d_in[8];
    const float* ln_ffn_g = (const float*)d_in[9];
    const float* ln_ffn_b = (const float*)d_in[10];
    float* out = (float*)d_out;

    float *xn, *qkv, *x1, *xn2, *hid;
    cudaGetSymbolAddress((void**)&xn,  g_xn);
    cudaGetSymbolAddress((void**)&qkv, g_qkv);
    cudaGetSymbolAddress((void**)&x1,  g_x1);
    cudaGetSymbolAddress((void**)&xn2, g_xn2);
    cudaGetSymbolAddress((void**)&hid, g_hid);

    cudaFuncSetAttribute(attn_mma_kernel,
                         cudaFuncAttributeMaxDynamicSharedMemorySize, ATTN_SMEM);
    cudaFuncSetAttribute(tf32_gemm_kernel<0, false>,
                         cudaFuncAttributeMaxDynamicSharedMemorySize, GEMM_SMEM);
    cudaFuncSetAttribute(tf32_gemm_kernel<1, false>,
                         cudaFuncAttributeMaxDynamicSharedMemorySize, GEMM_SMEM);
    cudaFuncSetAttribute(tf32_gemm_kernel<0, true>,
                         cudaFuncAttributeMaxDynamicSharedMemorySize, GEMM_SMEM);

    // 1) LN1
    ln_kernel<<<ROWS, 256>>>(x, nullptr, ln_att_g, ln_att_b, xn, nullptr);

    // 2) QKV GEMM: [8192,512] x [512,1536]
    tf32_gemm_kernel<0, false><<<dim3(1536 / 128, ROWS / 128), 256, GEMM_SMEM>>>(
        xn, qkv_w, qkv_b, nullptr, qkv, Emb, 3 * Emb);

    // 3) attention
    attn_mma_kernel<<<dim3(Nseq / 64, Bsz * Hn), 128, ATTN_SMEM>>>(qkv, xn);

    // 4) residual + LN2
    ln_kernel<<<ROWS, 256>>>(xn, x, ln_ffn_g, ln_ffn_b, xn2, x1);

    // 5) FC1 + GELU
    tf32_gemm_kernel<1, false><<<dim3(HID / 128, ROWS / 128), 256, GEMM_SMEM>>>(
        xn2, fc1_w, fc1_b, nullptr, hid, Emb, HID);

    // 6) FC2 + bias + residual
    tf32_gemm_kernel<0, true><<<dim3(Emb / 128, ROWS / 128), 256, GEMM_SMEM>>>(
        hid, fc2_w, fc2_b, x1, out, HID, Emb);
}

// round 6
// speedup vs baseline: 1.1463x; 1.1463x over previous
#include <cuda_runtime.h>
#include <math.h>
#include <stdint.h>

#define Bsz   4
#define Nseq  2048
#define Emb   512
#define Hn    8
#define HDm   64
#define HID   1536
#define ROWS  (Bsz * Nseq)   // 8192

// ---------------- scratch (device globals; no allocation allowed) ----------
__device__ float g_xn [ROWS * Emb];
__device__ float g_qkv[ROWS * 3 * Emb];
__device__ float g_x1 [ROWS * Emb];
__device__ float g_xn2[ROWS * Emb];
__device__ float g_hid[ROWS * HID];

// ---------------- LayerNorm (optionally fused residual add) ----------------
__global__ void __launch_bounds__(256) ln_kernel(
    const float* __restrict__ x, const float* __restrict__ resid,
    const float* __restrict__ g, const float* __restrict__ bb,
    float* __restrict__ out, float* __restrict__ xsum)
{
    int row = blockIdx.x;
    int tid = threadIdx.x;
    const float2* xr = (const float2*)(x + (size_t)row * Emb);
    float2 v = xr[tid];
    if (resid) {
        const float2* rr = (const float2*)(resid + (size_t)row * Emb);
        float2 r = rr[tid];
        v.x += r.x; v.y += r.y;
        ((float2*)(xsum + (size_t)row * Emb))[tid] = v;
    }
    float s  = v.x + v.y;
    float sq = v.x * v.x + v.y * v.y;
    #pragma unroll
    for (int o = 16; o > 0; o >>= 1) {
        s  += __shfl_xor_sync(0xffffffffu, s,  o);
        sq += __shfl_xor_sync(0xffffffffu, sq, o);
    }
    __shared__ float ss[8], sqs[8];
    int w = tid >> 5, lane = tid & 31;
    if (lane == 0) { ss[w] = s; sqs[w] = sq; }
    __syncthreads();
    float st = 0.f, sqt = 0.f;
    #pragma unroll
    for (int i = 0; i < 8; i++) { st += ss[i]; sqt += sqs[i]; }
    float mu   = st * (1.0f / Emb);
    float var  = sqt * (1.0f / Emb) - mu * mu;
    float rstd = rsqrtf(var + 1e-5f);
    float2 gg  = ((const float2*)g)[tid];
    float2 bv  = ((const float2*)bb)[tid];
    float2 o;
    o.x = (v.x - mu) * rstd * gg.x + bv.x;
    o.y = (v.y - mu) * rstd * gg.y + bv.y;
    ((float2*)(out + (size_t)row * Emb))[tid] = o;
}

// ---------------- GELU / TF32 helpers ---------------------------------------
__device__ __forceinline__ float gelu_exact(float x) {
    return 0.5f * x * (1.0f + erff(x * 0.70710678118654752f));
}
__device__ __forceinline__ float tf32r(float x) {
    unsigned u;
    asm("cvt.rna.tf32.f32 %0, %1;" : "=r"(u) : "f"(x));
    return __uint_as_float(u);
}
__device__ __forceinline__ float4 tf32r4(float4 v) {
    float4 r;
    r.x = tf32r(v.x); r.y = tf32r(v.y); r.z = tf32r(v.z); r.w = tf32r(v.w);
    return r;
}
__device__ __forceinline__ void mma_tf32(
    float* d, const unsigned* a, const unsigned* b)
{
    asm volatile(
        "mma.sync.aligned.m16n8k8.row.col.f32.tf32.tf32.f32 "
        "{%0,%1,%2,%3}, {%4,%5,%6,%7}, {%8,%9}, {%0,%1,%2,%3};"
        : "+f"(d[0]), "+f"(d[1]), "+f"(d[2]), "+f"(d[3])
        : "r"(a[0]), "r"(a[1]), "r"(a[2]), "r"(a[3]),
          "r"(b[0]), "r"(b[1]));
}

// ---------------- TF32 mma.sync GEMM: CTA 128x256, warp tile 64x64 -----------
// C[M,N] = A[M,K] @ W[K,N] + bias (+gelu)(+resid)
// 8 warps = 2 (wm) x 4 (wn).  BK=32, register-staged double buffer (R2-style).
// As stride 36 (=4 mod 32), Bs stride 264 (=8 mod 32): frag loads conflict-free.
#define AST 36
#define BST 264
#define GEMM_SMEM ((2 * 128 * AST + 2 * 32 * BST) * 4)   // 104448 B

template<int ACT, bool RES>
__global__ void __launch_bounds__(256) tf32_gemm_kernel(
    const float* __restrict__ A, const float* __restrict__ W,
    const float* __restrict__ bias, const float* __restrict__ R,
    float* __restrict__ C, int K, int N)
{
    extern __shared__ float sm[];
    float* As = sm;                    // [2][128*AST]
    float* Bs = sm + 2 * 128 * AST;    // [2][32*BST]

    int tid  = threadIdx.x;
    int lane = tid & 31;
    int wid  = tid >> 5;
    int wm   = wid & 1;        // warp row (0..1) -> rows wm*64
    int wn   = wid >> 1;       // warp col (0..3) -> cols wn*64
    int bm   = blockIdx.y, bn = blockIdx.x;
    int g    = lane >> 2, q = lane & 3;

    // global load mapping
    int ar  = tid >> 3;            // A row 0..31 (+32r)
    int ac  = (tid & 7) * 4;       // A col (k) float4
    int br  = tid >> 6;            // B row (k) 0..3 (+4r)
    int bc  = (tid & 63) * 4;      // B col float4 (0..252)
    const float* Ag = A + ((size_t)(bm * 128 + ar)) * K + ac;
    const float* Wg = W + (size_t)br * N + (size_t)bn * 256 + bc;

    float4 pa[4], pb[8];
    #define LOAD_TILE(k0)                                                   \
        {                                                                   \
            _Pragma("unroll")                                               \
            for (int r = 0; r < 4; r++)                                     \
                pa[r] = *(const float4*)(Ag + (size_t)(r * 32) * K + (k0)); \
            _Pragma("unroll")                                               \
            for (int r = 0; r < 8; r++)                                     \
                pb[r] = *(const float4*)(Wg + (size_t)((k0) + r * 4) * N);  \
        }
    #define STORE_TILE(buf)                                                 \
        {                                                                   \
            _Pragma("unroll")                                               \
            for (int r = 0; r < 4; r++)                                     \
                *(float4*)&As[(buf) * 128 * AST + (ar + r * 32) * AST + ac] \
                    = tf32r4(pa[r]);                                        \
            _Pragma("unroll")                                               \
            for (int r = 0; r < 8; r++)                                     \
                *(float4*)&Bs[(buf) * 32 * BST + (br + r * 4) * BST + bc]   \
                    = tf32r4(pb[r]);                                        \
        }

    float acc[4][8][4] = {};

    LOAD_TILE(0);
    STORE_TILE(0);
    __syncthreads();

    int NT = K / 32;
    for (int it = 0; it < NT; it++) {
        int nxt = it + 1;
        if (nxt < NT) LOAD_TILE(nxt * 32);

        const unsigned* asu = (const unsigned*)(As + (it & 1) * 128 * AST)
                              + wm * 64 * AST;
        const unsigned* bsu = (const unsigned*)(Bs + (it & 1) * 32 * BST)
                              + wn * 64;
        #pragma unroll
        for (int k8 = 0; k8 < 4; k8++) {
            int kk = k8 * 8;
            unsigned a[4][4], b[8][2];
            #pragma unroll
            for (int mf = 0; mf < 4; mf++) {
                a[mf][0] = asu[(mf * 16 + g)     * AST + kk + q];
                a[mf][1] = asu[(mf * 16 + g + 8) * AST + kk + q];
                a[mf][2] = asu[(mf * 16 + g)     * AST + kk + q + 4];
                a[mf][3] = asu[(mf * 16 + g + 8) * AST + kk + q + 4];
            }
            #pragma unroll
            for (int nf = 0; nf < 8; nf++) {
                b[nf][0] = bsu[(kk + q)     * BST + nf * 8 + g];
                b[nf][1] = bsu[(kk + q + 4) * BST + nf * 8 + g];
            }
            #pragma unroll
            for (int mf = 0; mf < 4; mf++)
                #pragma unroll
                for (int nf = 0; nf < 8; nf++)
                    mma_tf32(acc[mf][nf], a[mf], b[nf]);
        }

        __syncthreads();
        if (nxt < NT) {
            STORE_TILE(nxt & 1);
            __syncthreads();
        }
    }

    // epilogue
    int row0 = bm * 128 + wm * 64 + g;
    int col0 = bn * 256 + wn * 64 + 2 * q;
    #pragma unroll
    for (int nf = 0; nf < 8; nf++) {
        int c = col0 + nf * 8;
        float bx = bias[c], by = bias[c + 1];
        #pragma unroll
        for (int mf = 0; mf < 4; mf++) {
            int r0 = row0 + mf * 16;
            float v0x = acc[mf][nf][0] + bx;
            float v0y = acc[mf][nf][1] + by;
            float v1x = acc[mf][nf][2] + bx;
            float v1y = acc[mf][nf][3] + by;
            if (ACT == 1) {
                v0x = gelu_exact(v0x); v0y = gelu_exact(v0y);
                v1x = gelu_exact(v1x); v1y = gelu_exact(v1y);
            }
            if (RES) {
                const float2 r0v = *(const float2*)&R[(size_t)r0 * N + c];
                const float2 r1v = *(const float2*)&R[(size_t)(r0 + 8) * N + c];
                v0x += r0v.x; v0y += r0v.y;
                v1x += r1v.x; v1y += r1v.y;
            }
            float2 o0 = {v0x, v0y}, o1 = {v1x, v1y};
            *(float2*)&C[(size_t)r0 * N + c]       = o0;
            *(float2*)&C[(size_t)(r0 + 8) * N + c] = o1;
        }
    }
    #undef LOAD_TILE
    #undef STORE_TILE
}

// ---------------- flash attention, TF32 mma.sync (verified R3) --------------
#define QST 68
#define KST 68
#define VST 72
#define PST 68
#define ATTN_SMEM ((64 * QST + 64 * KST + 64 * VST + 64 * PST) * 4)

__global__ void __launch_bounds__(128) attn_mma_kernel(
    const float* __restrict__ qkv, float* __restrict__ out)
{
    extern __shared__ float sm[];
    float* Qs = sm;
    float* Ks = Qs + 64 * QST;
    float* Vs = Ks + 64 * KST;
    float* Ps = Vs + 64 * VST;

    int tid  = threadIdx.x;
    int lane = tid & 31;
    int w    = tid >> 5;
    int g    = lane >> 2, q = lane & 3;

    int bh = blockIdx.y;
    int b  = bh >> 3, h = bh & 7;
    int q0 = blockIdx.x * 64;
    const float* base = qkv + (size_t)b * Nseq * (3 * Emb) + h * (3 * HDm);

    #pragma unroll
    for (int i = 0; i < 8; i++) {
        int fi  = tid + i * 128;
        int row = fi >> 4;
        int c4  = (fi & 15) * 4;
        float4 v = *(const float4*)(base + (size_t)(q0 + row) * (3 * Emb) + c4);
        *(float4*)&Qs[row * QST + c4] = tf32r4(v);
    }

    float O[8][4] = {};
    float m0 = -1e30f, m1 = -1e30f, l0 = 0.f, l1 = 0.f;

    for (int kb = 0; kb < Nseq / 64; kb++) {
        __syncthreads();
        #pragma unroll
        for (int i = 0; i < 8; i++) {
            int fi  = tid + i * 128;
            int row = fi >> 4;
            int c4  = (fi & 15) * 4;
            const float* gp = base + (size_t)(kb * 64 + row) * (3 * Emb);
            *(float4*)&Ks[row * KST + c4] = tf32r4(*(const float4*)(gp + HDm + c4));
            *(float4*)&Vs[row * VST + c4] = tf32r4(*(const float4*)(gp + 2 * HDm + c4));
        }
        __syncthreads();

        const unsigned* qsu = (const unsigned*)Qs + (w * 16) * QST;
        unsigned af[8][4];
        #pragma unroll
        for (int k8 = 0; k8 < 8; k8++) {
            int kk = k8 * 8;
            af[k8][0] = qsu[(g)     * QST + kk + q];
            af[k8][1] = qsu[(g + 8) * QST + kk + q];
            af[k8][2] = qsu[(g)     * QST + kk + q + 4];
            af[k8][3] = qsu[(g + 8) * QST + kk + q + 4];
        }
        float sacc[8][4] = {};
        const unsigned* ksu = (const unsigned*)Ks;
        #pragma unroll
        for (int nf = 0; nf < 8; nf++) {
            #pragma unroll
            for (int k8 = 0; k8 < 8; k8++) {
                unsigned bfr[2];
                bfr[0] = ksu[(nf * 8 + g) * KST + k8 * 8 + q];
                bfr[1] = ksu[(nf * 8 + g) * KST + k8 * 8 + q + 4];
                mma_tf32(sacc[nf], af[k8], bfr);
            }
        }

        float mx0 = -1e30f, mx1 = -1e30f;
        #pragma unroll
        for (int nf = 0; nf < 8; nf++) {
            sacc[nf][0] *= 0.125f; sacc[nf][1] *= 0.125f;
            sacc[nf][2] *= 0.125f; sacc[nf][3] *= 0.125f;
            mx0 = fmaxf(mx0, fmaxf(sacc[nf][0], sacc[nf][1]));
            mx1 = fmaxf(mx1, fmaxf(sacc[nf][2], sacc[nf][3]));
        }
        mx0 = fmaxf(mx0, __shfl_xor_sync(0xffffffffu, mx0, 1));
        mx0 = fmaxf(mx0, __shfl_xor_sync(0xffffffffu, mx0, 2));
        mx1 = fmaxf(mx1, __shfl_xor_sync(0xffffffffu, mx1, 1));
        mx1 = fmaxf(mx1, __shfl_xor_sync(0xffffffffu, mx1, 2));

        float mn0 = fmaxf(m0, mx0), mn1 = fmaxf(m1, mx1);
        float al0 = __expf(m0 - mn0), al1 = __expf(m1 - mn1);
        m0 = mn0; m1 = mn1;

        float rs0 = 0.f, rs1 = 0.f;
        float* pw = Ps + (w * 16) * PST;
        #pragma unroll
        for (int nf = 0; nf < 8; nf++) {
            float p0 = __expf(sacc[nf][0] - mn0);
            float p1 = __expf(sacc[nf][1] - mn0);
            float p2 = __expf(sacc[nf][2] - mn1);
            float p3 = __expf(sacc[nf][3] - mn1);
            rs0 += p0 + p1; rs1 += p2 + p3;
            pw[(g)     * PST + nf * 8 + 2 * q]     = tf32r(p0);
            pw[(g)     * PST + nf * 8 + 2 * q + 1] = tf32r(p1);
            pw[(g + 8) * PST + nf * 8 + 2 * q]     = tf32r(p2);
            pw[(g + 8) * PST + nf * 8 + 2 * q + 1] = tf32r(p3);
        }
        rs0 += __shfl_xor_sync(0xffffffffu, rs0, 1);
        rs0 += __shfl_xor_sync(0xffffffffu, rs0, 2);
        rs1 += __shfl_xor_sync(0xffffffffu, rs1, 1);
        rs1 += __shfl_xor_sync(0xffffffffu, rs1, 2);
        l0 = l0 * al0 + rs0;
        l1 = l1 * al1 + rs1;

        #pragma unroll
        for (int df = 0; df < 8; df++) {
            O[df][0] *= al0; O[df][1] *= al0;
            O[df][2] *= al1; O[df][3] *= al1;
        }
        __syncwarp();

        const unsigned* psu = (const unsigned*)Ps + (w * 16) * PST;
        unsigned pf[8][4];
        #pragma unroll
        for (int k8 = 0; k8 < 8; k8++) {
            int kk = k8 * 8;
            pf[k8][0] = psu[(g)     * PST + kk + q];
            pf[k8][1] = psu[(g + 8) * PST + kk + q];
            pf[k8][2] = psu[(g)     * PST + kk + q + 4];
            pf[k8][3] = psu[(g + 8) * PST + kk + q + 4];
        }
        const unsigned* vsu = (const unsigned*)Vs;
        #pragma unroll
        for (int df = 0; df < 8; df++) {
            #pragma unroll
            for (int k8 = 0; k8 < 8; k8++) {
                unsigned bfr[2];
                bfr[0] = vsu[(k8 * 8 + q)     * VST + df * 8 + g];
                bfr[1] = vsu[(k8 * 8 + q + 4) * VST + df * 8 + g];
                mma_tf32(O[df], pf[k8], bfr);
            }
        }
    }

    float inv0 = 1.0f / l0, inv1 = 1.0f / l1;
    int r0 = q0 + w * 16 + g;
    int r1 = r0 + 8;
    #pragma unroll
    for (int df = 0; df < 8; df++) {
        int c = h * HDm + df * 8 + 2 * q;
        float2 o0 = {O[df][0] * inv0, O[df][1] * inv0};
        float2 o1 = {O[df][2] * inv1, O[df][3] * inv1};
        *(float2*)&out[((size_t)b * Nseq + r0) * Emb + c] = o0;
        *(float2*)&out[((size_t)b * Nseq + r1) * Emb + c] = o1;
    }
}

// ---------------- launch ------------------------------------------------------
extern "C" void kernel_launch(void* const* d_in, const int* in_sizes, int n_in,
                              void* d_out, int out_size)
{
    (void)in_sizes; (void)n_in; (void)out_size;
    const float* x        = (const float*)d_in[0];
    const float* qkv_w    = (const float*)d_in[1];
    const float* qkv_b    = (const float*)d_in[2];
    const float* fc1_w    = (const float*)d_in[3];
    const float* fc1_b    = (const float*)d_in[4];
    const float* fc2_w    = (const float*)d_in[5];
    const float* fc2_b    = (const float*)d_in[6];
    const float* ln_att_g = (const float*)d_in[7];
    const float* ln_att_b = (const float*)d_in[8];
    const float* ln_ffn_g = (const float*)d_in[9];
    const float* ln_ffn_b = (const float*)d_in[10];
    float* out = (float*)d_out;

    float *xn, *qkv, *x1, *xn2, *hid;
    cudaGetSymbolAddress((void**)&xn,  g_xn);
    cudaGetSymbolAddress((void**)&qkv, g_qkv);
    cudaGetSymbolAddress((void**)&x1,  g_x1);
    cudaGetSymbolAddress((void**)&xn2, g_xn2);
    cudaGetSymbolAddress((void**)&hid, g_hid);

    cudaFuncSetAttribute(attn_mma_kernel,
                         cudaFuncAttributeMaxDynamicSharedMemorySize, ATTN_SMEM);
    cudaFuncSetAttribute(tf32_gemm_kernel<0, false>,
                         cudaFuncAttributeMaxDynamicSharedMemorySize, GEMM_SMEM);
    cudaFuncSetAttribute(tf32_gemm_kernel<1, false>,
                         cudaFuncAttributeMaxDynamicSharedMemorySize, GEMM_SMEM);
    cudaFuncSetAttribute(tf32_gemm_kernel<0, true>,
                         cudaFuncAttributeMaxDynamicSharedMemorySize, GEMM_SMEM);

    // 1) LN1
    ln_kernel<<<ROWS, 256>>>(x, nullptr, ln_att_g, ln_att_b, xn, nullptr);

    // 2) QKV GEMM: [8192,512] x [512,1536], CTA tile 128x256
    tf32_gemm_kernel<0, false><<<dim3(1536 / 256, ROWS / 128), 256, GEMM_SMEM>>>(
        xn, qkv_w, qkv_b, nullptr, qkv, Emb, 3 * Emb);

    // 3) attention
    attn_mma_kernel<<<dim3(Nseq / 64, Bsz * Hn), 128, ATTN_SMEM>>>(qkv, xn);

    // 4) residual + LN2
    ln_kernel<<<ROWS, 256>>>(xn, x, ln_ffn_g, ln_ffn_b, xn2, x1);

    // 5) FC1 + GELU
    tf32_gemm_kernel<1, false><<<dim3(HID / 256, ROWS / 128), 256, GEMM_SMEM>>>(
        xn2, fc1_w, fc1_b, nullptr, hid, Emb, HID);

    // 6) FC2 + bias + residual
    tf32_gemm_kernel<0, true><<<dim3(Emb / 256, ROWS / 128), 256, GEMM_SMEM>>>(
        hid, fc2_w, fc2_b, x1, out, HID, Emb);
}

// round 7
// speedup vs baseline: 1.3030x; 1.1367x over previous
#include <cuda_runtime.h>
#include <cuda_fp16.h>
#include <math.h>
#include <stdint.h>

#define Bsz   4
#define Nseq  2048
#define Emb   512
#define Hn    8
#define HDm   64
#define HID   1536
#define ROWS  (Bsz * Nseq)   // 8192

// ---------------- scratch (device globals; no allocation allowed) ----------
__device__ __half g_xnh [ROWS * Emb];        // LN1 out (fp16)
__device__ float  g_qkv [ROWS * 3 * Emb];    // QKV GEMM out (fp32)
__device__ float  g_attn[ROWS * Emb];        // attention out (fp32)
__device__ float  g_x1  [ROWS * Emb];        // residual after attention (fp32)
__device__ __half g_xn2h[ROWS * Emb];        // LN2 out (fp16)
__device__ __half g_hidh[ROWS * HID];        // FFN hidden (fp16)
__device__ __half g_wt1 [3 * Emb * Emb];     // qkv_w^T fp16 [1536,512]
__device__ __half g_wt2 [HID * Emb];         // fc1_w^T fp16 [1536,512]
__device__ __half g_wt3 [Emb * HID];         // fc2_w^T fp16 [512,1536]

// ---------------- helpers ----------------------------------------------------
__device__ __forceinline__ float gelu_exact(float x) {
    return 0.5f * x * (1.0f + erff(x * 0.70710678118654752f));
}
__device__ __forceinline__ float tf32r(float x) {
    unsigned u;
    asm("cvt.rna.tf32.f32 %0, %1;" : "=r"(u) : "f"(x));
    return __uint_as_float(u);
}
__device__ __forceinline__ float4 tf32r4(float4 v) {
    float4 r;
    r.x = tf32r(v.x); r.y = tf32r(v.y); r.z = tf32r(v.z); r.w = tf32r(v.w);
    return r;
}
__device__ __forceinline__ void mma_tf32(
    float* d, const unsigned* a, const unsigned* b)
{
    asm volatile(
        "mma.sync.aligned.m16n8k8.row.col.f32.tf32.tf32.f32 "
        "{%0,%1,%2,%3}, {%4,%5,%6,%7}, {%8,%9}, {%0,%1,%2,%3};"
        : "+f"(d[0]), "+f"(d[1]), "+f"(d[2]), "+f"(d[3])
        : "r"(a[0]), "r"(a[1]), "r"(a[2]), "r"(a[3]),
          "r"(b[0]), "r"(b[1]));
}
__device__ __forceinline__ void mma_f16(
    float* d, const unsigned* a, const unsigned* b)
{
    asm volatile(
        "mma.sync.aligned.m16n8k16.row.col.f32.f16.f16.f32 "
        "{%0,%1,%2,%3}, {%4,%5,%6,%7}, {%8,%9}, {%0,%1,%2,%3};"
        : "+f"(d[0]), "+f"(d[1]), "+f"(d[2]), "+f"(d[3])
        : "r"(a[0]), "r"(a[1]), "r"(a[2]), "r"(a[3]),
          "r"(b[0]), "r"(b[1]));
}

// ---------------- LayerNorm: fp32 in (+optional resid), fp16 out -------------
__global__ void __launch_bounds__(256) ln_kernel(
    const float* __restrict__ x, const float* __restrict__ resid,
    const float* __restrict__ g, const float* __restrict__ bb,
    __half* __restrict__ out, float* __restrict__ xsum)
{
    int row = blockIdx.x;
    int tid = threadIdx.x;
    const float2* xr = (const float2*)(x + (size_t)row * Emb);
    float2 v = xr[tid];
    if (resid) {
        const float2* rr = (const float2*)(resid + (size_t)row * Emb);
        float2 r = rr[tid];
        v.x += r.x; v.y += r.y;
        ((float2*)(xsum + (size_t)row * Emb))[tid] = v;
    }
    float s  = v.x + v.y;
    float sq = v.x * v.x + v.y * v.y;
    #pragma unroll
    for (int o = 16; o > 0; o >>= 1) {
        s  += __shfl_xor_sync(0xffffffffu, s,  o);
        sq += __shfl_xor_sync(0xffffffffu, sq, o);
    }
    __shared__ float ss[8], sqs[8];
    int w = tid >> 5, lane = tid & 31;
    if (lane == 0) { ss[w] = s; sqs[w] = sq; }
    __syncthreads();
    float st = 0.f, sqt = 0.f;
    #pragma unroll
    for (int i = 0; i < 8; i++) { st += ss[i]; sqt += sqs[i]; }
    float mu   = st * (1.0f / Emb);
    float var  = sqt * (1.0f / Emb) - mu * mu;
    float rstd = rsqrtf(var + 1e-5f);
    float2 gg  = ((const float2*)g)[tid];
    float2 bv  = ((const float2*)bb)[tid];
    float ox = (v.x - mu) * rstd * gg.x + bv.x;
    float oy = (v.y - mu) * rstd * gg.y + bv.y;
    ((__half2*)(out + (size_t)row * Emb))[tid] = __floats2half2_rn(ox, oy);
}

// ---------------- weight transpose: W[K,N] fp32 -> Wt[N,K] fp16 ---------------
__global__ void __launch_bounds__(256) transpose_h_kernel(
    const float* __restrict__ W, __half* __restrict__ Wt, int K, int N)
{
    __shared__ float t[32][33];
    int tx = threadIdx.x & 31, ty = threadIdx.x >> 5;   // ty 0..7
    int k0 = blockIdx.y * 32, n0 = blockIdx.x * 32;
    #pragma unroll
    for (int i = 0; i < 4; i++)
        t[ty + 8 * i][tx] = W[(size_t)(k0 + ty + 8 * i) * N + n0 + tx];
    __syncthreads();
    #pragma unroll
    for (int i = 0; i < 4; i++)
        Wt[(size_t)(n0 + ty + 8 * i) * K + k0 + tx] =
            __float2half_rn(t[tx][ty + 8 * i]);
}

// ---------------- fp16 mma.sync GEMM: CTA 128x256, warp tile 64x64 ------------
// C[M,N] = A[M,K](fp16) @ Wt[N,K](fp16)^T + bias (+gelu)(+resid)
// BK=64 (rows of 64 fp16 = 32 words + pad -> stride 36 words, =4 mod 32:
// frag LDS conflict-free, same proof as verified tf32 layout).
// 8 warps = 2(wm) x 4(wn).  Register-staged double buffer (R2/R6 structure).
#define RSW 36                                  // row stride in 4B words
#define ATW (128 * RSW)                         // A tile words
#define BTW (256 * RSW)                         // B tile words
#define GEMM_SMEM ((2 * ATW + 2 * BTW) * 4)     // 110592 B

template<int ACT, int OUTH, bool RES>
__global__ void __launch_bounds__(256) h16_gemm_kernel(
    const __half* __restrict__ A, const __half* __restrict__ Bt,
    const float* __restrict__ bias, const float* __restrict__ R,
    void* __restrict__ Cv, int K, int N)
{
    extern __shared__ unsigned smw[];
    unsigned* As = smw;                 // [2][ATW]
    unsigned* Bs = smw + 2 * ATW;       // [2][BTW]

    int tid  = threadIdx.x;
    int lane = tid & 31;
    int wid  = tid >> 5;
    int wm   = wid & 1;        // rows wm*64
    int wn   = wid >> 1;       // cols wn*64
    int bm   = blockIdx.y, bn = blockIdx.x;
    int g    = lane >> 2, q = lane & 3;

    // global load mapping (per 128x64(A) / 256x64(B) fp16 tile)
    int ar = tid >> 1;             // A row 0..127
    int ah = (tid & 1) * 32;       // fp16 offset within row (0 or 32)
    const __half* Ag = A + (size_t)(bm * 128 + ar) * K + ah;
    const __half* Bg = Bt + (size_t)(bn * 256 + tid) * K;

    uint4 pa[4], pb[8];
    #define LOAD_TILE(k0)                                                    \
        {                                                                    \
            _Pragma("unroll")                                                \
            for (int j = 0; j < 4; j++)                                      \
                pa[j] = *(const uint4*)(Ag + (k0) + j * 8);                  \
            _Pragma("unroll")                                                \
            for (int j = 0; j < 8; j++)                                      \
                pb[j] = *(const uint4*)(Bg + (k0) + j * 8);                  \
        }
    #define STORE_TILE(buf)                                                  \
        {                                                                    \
            _Pragma("unroll")                                                \
            for (int j = 0; j < 4; j++)                                      \
                *(uint4*)&As[(buf) * ATW + ar * RSW + (tid & 1) * 16 + j * 4]\
                    = pa[j];                                                 \
            _Pragma("unroll")                                                \
            for (int j = 0; j < 8; j++)                                      \
                *(uint4*)&Bs[(buf) * BTW + tid * RSW + j * 4] = pb[j];       \
        }

    float acc[4][8][4] = {};

    LOAD_TILE(0);
    STORE_TILE(0);
    __syncthreads();

    int NT = K / 64;
    for (int it = 0; it < NT; it++) {
        int nxt = it + 1;
        if (nxt < NT) LOAD_TILE(nxt * 64);

        const unsigned* asu = As + (it & 1) * ATW + (wm * 64) * RSW;
        const unsigned* bsu = Bs + (it & 1) * BTW + (wn * 64) * RSW;
        #pragma unroll
        for (int kg = 0; kg < 4; kg++) {
            int kk = kg * 8;
            unsigned a[4][4], b[8][2];
            #pragma unroll
            for (int mf = 0; mf < 4; mf++) {
                a[mf][0] = asu[(mf * 16 + g)     * RSW + kk + q];
                a[mf][1] = asu[(mf * 16 + g + 8) * RSW + kk + q];
                a[mf][2] = asu[(mf * 16 + g)     * RSW + kk + q + 4];
                a[mf][3] = asu[(mf * 16 + g + 8) * RSW + kk + q + 4];
            }
            #pragma unroll
            for (int nf = 0; nf < 8; nf++) {
                b[nf][0] = bsu[(nf * 8 + g) * RSW + kk + q];
                b[nf][1] = bsu[(nf * 8 + g) * RSW + kk + q + 4];
            }
            #pragma unroll
            for (int mf = 0; mf < 4; mf++)
                #pragma unroll
                for (int nf = 0; nf < 8; nf++)
                    mma_f16(acc[mf][nf], a[mf], b[nf]);
        }

        __syncthreads();
        if (nxt < NT) {
            STORE_TILE(nxt & 1);
            __syncthreads();
        }
    }

    // epilogue
    int row0 = bm * 128 + wm * 64 + g;
    int col0 = bn * 256 + wn * 64 + 2 * q;
    #pragma unroll
    for (int nf = 0; nf < 8; nf++) {
        int c = col0 + nf * 8;
        float bx = bias[c], by = bias[c + 1];
        #pragma unroll
        for (int mf = 0; mf < 4; mf++) {
            int r0 = row0 + mf * 16;
            float v0x = acc[mf][nf][0] + bx;
            float v0y = acc[mf][nf][1] + by;
            float v1x = acc[mf][nf][2] + bx;
            float v1y = acc[mf][nf][3] + by;
            if (ACT == 1) {
                v0x = gelu_exact(v0x); v0y = gelu_exact(v0y);
                v1x = gelu_exact(v1x); v1y = gelu_exact(v1y);
            }
            if (OUTH) {
                __half* C = (__half*)Cv;
                *(__half2*)&C[(size_t)r0 * N + c]       = __floats2half2_rn(v0x, v0y);
                *(__half2*)&C[(size_t)(r0 + 8) * N + c] = __floats2half2_rn(v1x, v1y);
            } else {
                float* C = (float*)Cv;
                if (RES) {
                    const float2 r0v = *(const float2*)&R[(size_t)r0 * N + c];
                    const float2 r1v = *(const float2*)&R[(size_t)(r0 + 8) * N + c];
                    v0x += r0v.x; v0y += r0v.y;
                    v1x += r1v.x; v1y += r1v.y;
                }
                float2 o0 = {v0x, v0y}, o1 = {v1x, v1y};
                *(float2*)&C[(size_t)r0 * N + c]       = o0;
                *(float2*)&C[(size_t)(r0 + 8) * N + c] = o1;
            }
        }
    }
    #undef LOAD_TILE
    #undef STORE_TILE
}

// ---------------- flash attention, TF32 mma.sync (verified R3/R6) ------------
#define QST 68
#define KST 68
#define VST 72
#define PST 68
#define ATTN_SMEM ((64 * QST + 64 * KST + 64 * VST + 64 * PST) * 4)

__global__ void __launch_bounds__(128) attn_mma_kernel(
    const float* __restrict__ qkv, float* __restrict__ out)
{
    extern __shared__ float sm[];
    float* Qs = sm;
    float* Ks = Qs + 64 * QST;
    float* Vs = Ks + 64 * KST;
    float* Ps = Vs + 64 * VST;

    int tid  = threadIdx.x;
    int lane = tid & 31;
    int w    = tid >> 5;
    int g    = lane >> 2, q = lane & 3;

    int bh = blockIdx.y;
    int b  = bh >> 3, h = bh & 7;
    int q0 = blockIdx.x * 64;
    const float* base = qkv + (size_t)b * Nseq * (3 * Emb) + h * (3 * HDm);

    #pragma unroll
    for (int i = 0; i < 8; i++) {
        int fi  = tid + i * 128;
        int row = fi >> 4;
        int c4  = (fi & 15) * 4;
        float4 v = *(const float4*)(base + (size_t)(q0 + row) * (3 * Emb) + c4);
        *(float4*)&Qs[row * QST + c4] = tf32r4(v);
    }

    float O[8][4] = {};
    float m0 = -1e30f, m1 = -1e30f, l0 = 0.f, l1 = 0.f;

    for (int kb = 0; kb < Nseq / 64; kb++) {
        __syncthreads();
        #pragma unroll
        for (int i = 0; i < 8; i++) {
            int fi  = tid + i * 128;
            int row = fi >> 4;
            int c4  = (fi & 15) * 4;
            const float* gp = base + (size_t)(kb * 64 + row) * (3 * Emb);
            *(float4*)&Ks[row * KST + c4] = tf32r4(*(const float4*)(gp + HDm + c4));
            *(float4*)&Vs[row * VST + c4] = tf32r4(*(const float4*)(gp + 2 * HDm + c4));
        }
        __syncthreads();

        const unsigned* qsu = (const unsigned*)Qs + (w * 16) * QST;
        unsigned af[8][4];
        #pragma unroll
        for (int k8 = 0; k8 < 8; k8++) {
            int kk = k8 * 8;
            af[k8][0] = qsu[(g)     * QST + kk + q];
            af[k8][1] = qsu[(g + 8) * QST + kk + q];
            af[k8][2] = qsu[(g)     * QST + kk + q + 4];
            af[k8][3] = qsu[(g + 8) * QST + kk + q + 4];
        }
        float sacc[8][4] = {};
        const unsigned* ksu = (const unsigned*)Ks;
        #pragma unroll
        for (int nf = 0; nf < 8; nf++) {
            #pragma unroll
            for (int k8 = 0; k8 < 8; k8++) {
                unsigned bfr[2];
                bfr[0] = ksu[(nf * 8 + g) * KST + k8 * 8 + q];
                bfr[1] = ksu[(nf * 8 + g) * KST + k8 * 8 + q + 4];
                mma_tf32(sacc[nf], af[k8], bfr);
            }
        }

        float mx0 = -1e30f, mx1 = -1e30f;
        #pragma unroll
        for (int nf = 0; nf < 8; nf++) {
            sacc[nf][0] *= 0.125f; sacc[nf][1] *= 0.125f;
            sacc[nf][2] *= 0.125f; sacc[nf][3] *= 0.125f;
            mx0 = fmaxf(mx0, fmaxf(sacc[nf][0], sacc[nf][1]));
            mx1 = fmaxf(mx1, fmaxf(sacc[nf][2], sacc[nf][3]));
        }
        mx0 = fmaxf(mx0, __shfl_xor_sync(0xffffffffu, mx0, 1));
        mx0 = fmaxf(mx0, __shfl_xor_sync(0xffffffffu, mx0, 2));
        mx1 = fmaxf(mx1, __shfl_xor_sync(0xffffffffu, mx1, 1));
        mx1 = fmaxf(mx1, __shfl_xor_sync(0xffffffffu, mx1, 2));

        float mn0 = fmaxf(m0, mx0), mn1 = fmaxf(m1, mx1);
        float al0 = __expf(m0 - mn0), al1 = __expf(m1 - mn1);
        m0 = mn0; m1 = mn1;

        float rs0 = 0.f, rs1 = 0.f;
        float* pw = Ps + (w * 16) * PST;
        #pragma unroll
        for (int nf = 0; nf < 8; nf++) {
            float p0 = __expf(sacc[nf][0] - mn0);
            float p1 = __expf(sacc[nf][1] - mn0);
            float p2 = __expf(sacc[nf][2] - mn1);
            float p3 = __expf(sacc[nf][3] - mn1);
            rs0 += p0 + p1; rs1 += p2 + p3;
            pw[(g)     * PST + nf * 8 + 2 * q]     = tf32r(p0);
            pw[(g)     * PST + nf * 8 + 2 * q + 1] = tf32r(p1);
            pw[(g + 8) * PST + nf * 8 + 2 * q]     = tf32r(p2);
            pw[(g + 8) * PST + nf * 8 + 2 * q + 1] = tf32r(p3);
        }
        rs0 += __shfl_xor_sync(0xffffffffu, rs0, 1);
        rs0 += __shfl_xor_sync(0xffffffffu, rs0, 2);
        rs1 += __shfl_xor_sync(0xffffffffu, rs1, 1);
        rs1 += __shfl_xor_sync(0xffffffffu, rs1, 2);
        l0 = l0 * al0 + rs0;
        l1 = l1 * al1 + rs1;

        #pragma unroll
        for (int df = 0; df < 8; df++) {
            O[df][0] *= al0; O[df][1] *= al0;
            O[df][2] *= al1; O[df][3] *= al1;
        }
        __syncwarp();

        const unsigned* psu = (const unsigned*)Ps + (w * 16) * PST;
        unsigned pf[8][4];
        #pragma unroll
        for (int k8 = 0; k8 < 8; k8++) {
            int kk = k8 * 8;
            pf[k8][0] = psu[(g)     * PST + kk + q];
            pf[k8][1] = psu[(g + 8) * PST + kk + q];
            pf[k8][2] = psu[(g)     * PST + kk + q + 4];
            pf[k8][3] = psu[(g + 8) * PST + kk + q + 4];
        }
        const unsigned* vsu = (const unsigned*)Vs;
        #pragma unroll
        for (int df = 0; df < 8; df++) {
            #pragma unroll
            for (int k8 = 0; k8 < 8; k8++) {
                unsigned bfr[2];
                bfr[0] = vsu[(k8 * 8 + q)     * VST + df * 8 + g];
                bfr[1] = vsu[(k8 * 8 + q + 4) * VST + df * 8 + g];
                mma_tf32(O[df], pf[k8], bfr);
            }
        }
    }

    float inv0 = 1.0f / l0, inv1 = 1.0f / l1;
    int r0 = q0 + w * 16 + g;
    int r1 = r0 + 8;
    #pragma unroll
    for (int df = 0; df < 8; df++) {
        int c = h * HDm + df * 8 + 2 * q;
        float2 o0 = {O[df][0] * inv0, O[df][1] * inv0};
        float2 o1 = {O[df][2] * inv1, O[df][3] * inv1};
        *(float2*)&out[((size_t)b * Nseq + r0) * Emb + c] = o0;
        *(float2*)&out[((size_t)b * Nseq + r1) * Emb + c] = o1;
    }
}

// ---------------- launch ------------------------------------------------------
extern "C" void kernel_launch(void* const* d_in, const int* in_sizes, int n_in,
                              void* d_out, int out_size)
{
    (void)in_sizes; (void)n_in; (void)out_size;
    const float* x        = (const float*)d_in[0];
    const float* qkv_w    = (const float*)d_in[1];
    const float* qkv_b    = (const float*)d_in[2];
    const float* fc1_w    = (const float*)d_in[3];
    const float* fc1_b    = (const float*)d_in[4];
    const float* fc2_w    = (const float*)d_in[5];
    const float* fc2_b    = (const float*)d_in[6];
    const float* ln_att_g = (const float*)d_in[7];
    const float* ln_att_b = (const float*)d_in[8];
    const float* ln_ffn_g = (const float*)d_in[9];
    const float* ln_ffn_b = (const float*)d_in[10];
    float* out = (float*)d_out;

    __half *xnh, *xn2h, *hidh, *wt1, *wt2, *wt3;
    float *qkv, *attn, *x1;
    cudaGetSymbolAddress((void**)&xnh,  g_xnh);
    cudaGetSymbolAddress((void**)&qkv,  g_qkv);
    cudaGetSymbolAddress((void**)&attn, g_attn);
    cudaGetSymbolAddress((void**)&x1,   g_x1);
    cudaGetSymbolAddress((void**)&xn2h, g_xn2h);
    cudaGetSymbolAddress((void**)&hidh, g_hidh);
    cudaGetSymbolAddress((void**)&wt1,  g_wt1);
    cudaGetSymbolAddress((void**)&wt2,  g_wt2);
    cudaGetSymbolAddress((void**)&wt3,  g_wt3);

    cudaFuncSetAttribute(attn_mma_kernel,
                         cudaFuncAttributeMaxDynamicSharedMemorySize, ATTN_SMEM);
    cudaFuncSetAttribute(h16_gemm_kernel<0, 0, false>,
                         cudaFuncAttributeMaxDynamicSharedMemorySize, GEMM_SMEM);
    cudaFuncSetAttribute(h16_gemm_kernel<1, 1, false>,
                         cudaFuncAttributeMaxDynamicSharedMemorySize, GEMM_SMEM);
    cudaFuncSetAttribute(h16_gemm_kernel<0, 0, true>,
                         cudaFuncAttributeMaxDynamicSharedMemorySize, GEMM_SMEM);

    // 0) weight transposes to fp16 [N,K]
    transpose_h_kernel<<<dim3(1536 / 32, 512 / 32), 256>>>(qkv_w, wt1, 512, 1536);
    transpose_h_kernel<<<dim3(1536 / 32, 512 / 32), 256>>>(fc1_w, wt2, 512, 1536);
    transpose_h_kernel<<<dim3(512 / 32, 1536 / 32), 256>>>(fc2_w, wt3, 1536, 512);

    // 1) LN1 -> fp16
    ln_kernel<<<ROWS, 256>>>(x, nullptr, ln_att_g, ln_att_b, xnh, nullptr);

    // 2) QKV GEMM (fp16 in, fp32 out): [8192,512] x [512,1536]
    h16_gemm_kernel<0, 0, false><<<dim3(1536 / 256, ROWS / 128), 256, GEMM_SMEM>>>(
        xnh, wt1, qkv_b, nullptr, qkv, Emb, 3 * Emb);

    // 3) attention (tf32, unchanged) -> fp32
    attn_mma_kernel<<<dim3(Nseq / 64, Bsz * Hn), 128, ATTN_SMEM>>>(qkv, attn);

    // 4) residual + LN2 -> xn2 fp16, x1 fp32
    ln_kernel<<<ROWS, 256>>>(attn, x, ln_ffn_g, ln_ffn_b, xn2h, x1);

    // 5) FC1 + GELU (fp16 in, fp16 out)
    h16_gemm_kernel<1, 1, false><<<dim3(HID / 256, ROWS / 128), 256, GEMM_SMEM>>>(
        xn2h, wt2, fc1_b, nullptr, hidh, Emb, HID);

    // 6) FC2 + bias + residual (fp16 in, fp32 out)
    h16_gemm_kernel<0, 0, true><<<dim3(Emb / 256, ROWS / 128), 256, GEMM_SMEM>>>(
        hidh, wt3, fc2_b, x1, out, HID, Emb);
}